// round 1
// baseline (speedup 1.0000x reference)
#include <cuda_runtime.h>
#include <cuda_bf16.h>
#include <cstdint>

// Problem constants (fixed by the dataset)
#define L_HOPS 5
#define D_DIM  32
#define E_MAX  131072

// Scratch: precomputed dots[e][l] = <edge_vector[l], edge_attr[e]>
__device__ float g_table[(size_t)E_MAX * L_HOPS];

// Reciprocal table for masked mean: 1/max(len,1), and 0 for len==0 (s==0 anyway)
__constant__ float c_inv[8] = {0.0f, 1.0f, 0.5f, 1.0f / 3.0f, 0.25f, 0.2f, 0.0f, 0.0f};

// ---------------------------------------------------------------------------
// Kernel 1: precompute per-(edge, hop) dot products.
// One thread per edge; edge row = 128 B read as 8x float4.
// ---------------------------------------------------------------------------
__global__ void __launch_bounds__(256) precompute_dots_kernel(
    const float* __restrict__ edge_attr,   // [E, 32]
    const float* __restrict__ edge_vector, // [5, 32]
    int E)
{
    __shared__ float sev[L_HOPS * D_DIM];  // 160 floats
    if (threadIdx.x < L_HOPS * D_DIM)
        sev[threadIdx.x] = edge_vector[threadIdx.x];
    __syncthreads();

    int e = blockIdx.x * blockDim.x + threadIdx.x;
    if (e >= E) return;

    const float4* row = reinterpret_cast<const float4*>(edge_attr + (size_t)e * D_DIM);

    float acc0 = 0.f, acc1 = 0.f, acc2 = 0.f, acc3 = 0.f, acc4 = 0.f;
#pragma unroll
    for (int i = 0; i < D_DIM / 4; i++) {
        float4 v = row[i];
#pragma unroll
        for (int c = 0; c < 4; c++) {
            float a = (c == 0) ? v.x : (c == 1) ? v.y : (c == 2) ? v.z : v.w;
            int d = i * 4 + c;
            acc0 = fmaf(a, sev[0 * D_DIM + d], acc0);
            acc1 = fmaf(a, sev[1 * D_DIM + d], acc1);
            acc2 = fmaf(a, sev[2 * D_DIM + d], acc2);
            acc3 = fmaf(a, sev[3 * D_DIM + d], acc3);
            acc4 = fmaf(a, sev[4 * D_DIM + d], acc4);
        }
    }

    float* t = g_table + (size_t)e * L_HOPS;
    t[0] = acc0; t[1] = acc1; t[2] = acc2; t[3] = acc3; t[4] = acc4;
}

// ---------------------------------------------------------------------------
// Kernel 2: per-pair masked mean over precomputed dots.
// One thread per pair: read 5 indices (coalesced stream), len, do up to 5
// predicated scalar gathers into the 2.6 MB L2-resident table.
// ---------------------------------------------------------------------------
__global__ void __launch_bounds__(256) pair_reduce_kernel(
    const int* __restrict__ path_edges,  // [P, 5]
    const int* __restrict__ path_len,    // [P]
    float* __restrict__ out,             // [P]
    int P)
{
    int p = blockIdx.x * blockDim.x + threadIdx.x;
    if (p >= P) return;

    int len = path_len[p];
    const int* row = path_edges + (size_t)p * L_HOPS;

    // Load all 5 indices unconditionally (in-bounds, coalesced-ish stream).
    int i0 = row[0];
    int i1 = row[1];
    int i2 = row[2];
    int i3 = row[3];
    int i4 = row[4];

    // Predicated gathers (issue in parallel for MLP).
    float v0 = (len > 0) ? __ldg(&g_table[(size_t)i0 * L_HOPS + 0]) : 0.f;
    float v1 = (len > 1) ? __ldg(&g_table[(size_t)i1 * L_HOPS + 1]) : 0.f;
    float v2 = (len > 2) ? __ldg(&g_table[(size_t)i2 * L_HOPS + 2]) : 0.f;
    float v3 = (len > 3) ? __ldg(&g_table[(size_t)i3 * L_HOPS + 3]) : 0.f;
    float v4 = (len > 4) ? __ldg(&g_table[(size_t)i4 * L_HOPS + 4]) : 0.f;

    float s = ((v0 + v1) + (v2 + v3)) + v4;
    out[p] = s * c_inv[len];  // len==0 -> s==0 and inv==0 -> 0
}

// ---------------------------------------------------------------------------
// Inputs (metadata order): x[N,32], edge_attr[E,32], edge_vector[5,32],
//                          path_edges[P,5] (int32), path_len[P] (int32)
// Output: float32 [N, N] flattened = P elements
// ---------------------------------------------------------------------------
extern "C" void kernel_launch(void* const* d_in, const int* in_sizes, int n_in,
                              void* d_out, int out_size)
{
    const float* edge_attr   = (const float*)d_in[1];
    const float* edge_vector = (const float*)d_in[2];
    const int*   path_edges  = (const int*)d_in[3];
    const int*   path_len    = (const int*)d_in[4];
    float*       out         = (float*)d_out;

    int E = in_sizes[1] / D_DIM;
    int P = out_size;

    {
        int threads = 256;
        int blocks = (E + threads - 1) / threads;
        precompute_dots_kernel<<<blocks, threads>>>(edge_attr, edge_vector, E);
    }
    {
        int threads = 256;
        int blocks = (P + threads - 1) / threads;
        pair_reduce_kernel<<<blocks, threads>>>(path_edges, path_len, out, P);
    }
}

// round 2
// speedup vs baseline: 1.0246x; 1.0246x over previous
#include <cuda_runtime.h>
#include <cuda_bf16.h>
#include <cstdint>

#define L_HOPS 5
#define D_DIM  32
#define E_MAX  131072

// Precomputed dots[e][l] = <edge_vector[l], edge_attr[e]>  (2.6 MB, L2-resident)
__device__ float g_table[(size_t)E_MAX * L_HOPS];

// 1/max(len,1); len==0 -> 0 (sum is 0 anyway)
__constant__ float c_inv[8] = {0.0f, 1.0f, 0.5f, 1.0f / 3.0f, 0.25f, 0.2f, 0.0f, 0.0f};

// ---------------------------------------------------------------------------
// Kernel 1: per-(edge, hop) dot products. One thread per edge (128 B row).
// ---------------------------------------------------------------------------
__global__ void __launch_bounds__(256) precompute_dots_kernel(
    const float* __restrict__ edge_attr,   // [E, 32]
    const float* __restrict__ edge_vector, // [5, 32]
    int E)
{
    __shared__ float sev[L_HOPS * D_DIM];
    if (threadIdx.x < L_HOPS * D_DIM)
        sev[threadIdx.x] = edge_vector[threadIdx.x];
    __syncthreads();

    int e = blockIdx.x * blockDim.x + threadIdx.x;
    if (e >= E) return;

    const float4* row = reinterpret_cast<const float4*>(edge_attr + (size_t)e * D_DIM);

    float acc0 = 0.f, acc1 = 0.f, acc2 = 0.f, acc3 = 0.f, acc4 = 0.f;
#pragma unroll
    for (int i = 0; i < D_DIM / 4; i++) {
        float4 v = row[i];
#pragma unroll
        for (int c = 0; c < 4; c++) {
            float a = (c == 0) ? v.x : (c == 1) ? v.y : (c == 2) ? v.z : v.w;
            int d = i * 4 + c;
            acc0 = fmaf(a, sev[0 * D_DIM + d], acc0);
            acc1 = fmaf(a, sev[1 * D_DIM + d], acc1);
            acc2 = fmaf(a, sev[2 * D_DIM + d], acc2);
            acc3 = fmaf(a, sev[3 * D_DIM + d], acc3);
            acc4 = fmaf(a, sev[4 * D_DIM + d], acc4);
        }
    }

    float* t = g_table + (size_t)e * L_HOPS;
    t[0] = acc0; t[1] = acc1; t[2] = acc2; t[3] = acc3; t[4] = acc4;
}

// ---------------------------------------------------------------------------
// Kernel 2: 4 pairs per thread. Vectorized index/len loads + float4 store,
// up to 20 predicated scalar gathers in flight per thread.
// ---------------------------------------------------------------------------
__device__ __forceinline__ float gat(int pred, int e, int l) {
    return pred ? __ldg(&g_table[(size_t)e * L_HOPS + l]) : 0.f;
}

__global__ void __launch_bounds__(256) pair_reduce_kernel4(
    const int* __restrict__ path_edges,  // [P, 5]
    const int* __restrict__ path_len,    // [P]
    float* __restrict__ out,             // [P]
    int Pq)                              // P / 4
{
    int t = blockIdx.x * blockDim.x + threadIdx.x;
    if (t >= Pq) return;

    // 4 pairs: 20 indices = 5 x int4 (80 B, 16B-aligned since 80 % 16 == 0)
    const int4* pe = reinterpret_cast<const int4*>(path_edges) + (size_t)t * 5;
    int4 a = __ldg(pe + 0);
    int4 b = __ldg(pe + 1);
    int4 c = __ldg(pe + 2);
    int4 d = __ldg(pe + 3);
    int4 e = __ldg(pe + 4);
    int4 ln = __ldg(reinterpret_cast<const int4*>(path_len) + t);

    // pair 0: a.x a.y a.z a.w b.x   len ln.x
    float s0 = gat(ln.x > 0, a.x, 0) + gat(ln.x > 1, a.y, 1)
             + gat(ln.x > 2, a.z, 2) + gat(ln.x > 3, a.w, 3)
             + gat(ln.x > 4, b.x, 4);
    // pair 1: b.y b.z b.w c.x c.y   len ln.y
    float s1 = gat(ln.y > 0, b.y, 0) + gat(ln.y > 1, b.z, 1)
             + gat(ln.y > 2, b.w, 2) + gat(ln.y > 3, c.x, 3)
             + gat(ln.y > 4, c.y, 4);
    // pair 2: c.z c.w d.x d.y d.z   len ln.z
    float s2 = gat(ln.z > 0, c.z, 0) + gat(ln.z > 1, c.w, 1)
             + gat(ln.z > 2, d.x, 2) + gat(ln.z > 3, d.y, 3)
             + gat(ln.z > 4, d.z, 4);
    // pair 3: d.w e.x e.y e.z e.w   len ln.w
    float s3 = gat(ln.w > 0, d.w, 0) + gat(ln.w > 1, e.x, 1)
             + gat(ln.w > 2, e.y, 2) + gat(ln.w > 3, e.z, 3)
             + gat(ln.w > 4, e.w, 4);

    float4 r;
    r.x = s0 * c_inv[ln.x & 7];
    r.y = s1 * c_inv[ln.y & 7];
    r.z = s2 * c_inv[ln.z & 7];
    r.w = s3 * c_inv[ln.w & 7];
    reinterpret_cast<float4*>(out)[t] = r;
}

// Scalar fallback for P not divisible by 4 (not hit for N=1024, kept for safety)
__global__ void pair_reduce_tail(
    const int* __restrict__ path_edges,
    const int* __restrict__ path_len,
    float* __restrict__ out,
    int start, int P)
{
    int p = start + blockIdx.x * blockDim.x + threadIdx.x;
    if (p >= P) return;
    int len = path_len[p];
    const int* row = path_edges + (size_t)p * L_HOPS;
    float s = 0.f;
#pragma unroll
    for (int l = 0; l < L_HOPS; l++)
        s += (len > l) ? __ldg(&g_table[(size_t)row[l] * L_HOPS + l]) : 0.f;
    out[p] = s * c_inv[len & 7];
}

// ---------------------------------------------------------------------------
// Inputs: x[N,32], edge_attr[E,32], edge_vector[5,32],
//         path_edges[P,5] (int32), path_len[P] (int32)  -> out float32 [P]
// ---------------------------------------------------------------------------
extern "C" void kernel_launch(void* const* d_in, const int* in_sizes, int n_in,
                              void* d_out, int out_size)
{
    const float* edge_attr   = (const float*)d_in[1];
    const float* edge_vector = (const float*)d_in[2];
    const int*   path_edges  = (const int*)d_in[3];
    const int*   path_len    = (const int*)d_in[4];
    float*       out         = (float*)d_out;

    int E = in_sizes[1] / D_DIM;
    int P = out_size;

    {
        int threads = 256;
        int blocks = (E + threads - 1) / threads;
        precompute_dots_kernel<<<blocks, threads>>>(edge_attr, edge_vector, E);
    }

    int Pq = P / 4;
    if (Pq > 0) {
        int threads = 256;
        int blocks = (Pq + threads - 1) / threads;
        pair_reduce_kernel4<<<blocks, threads>>>(path_edges, path_len, out, Pq);
    }
    int done = Pq * 4;
    if (done < P) {
        int rem = P - done;
        pair_reduce_tail<<<(rem + 255) / 256, 256>>>(path_edges, path_len, out, done, P);
    }
}